// round 11
// baseline (speedup 1.0000x reference)
#include <cuda_runtime.h>
#include <cuda_fp16.h>
#include <math.h>
#include <stdint.h>

#define BATCH 4
#define CFULL 512
#define HC 256
#define HH 128
#define WW 128
#define HW (HH*WW)

// x1 transposed + fp16: [b][p(pixel)][k(channel)], k contiguous
__device__ __align__(16) __half g_x1t[BATCH * HW * HC];
__device__ __align__(16) __half g_wa_h[CFULL * HC];   // wa[:, 0:256] in fp16
__device__ float g_pool[BATCH * HC * 4];
__device__ float g_base[BATCH * 4 * CFULL];

// ---------------------------------------------------------------------------
// Kernel 0: convert wa[:, 0:256] to fp16
// ---------------------------------------------------------------------------
__global__ __launch_bounds__(256) void waconv_kernel(const float* __restrict__ wa) {
    int i = blockIdx.x * 256 + threadIdx.x;     // 512*256 = 131072
    int o = i >> 8, k = i & 255;
    g_wa_h[i] = __float2half_rn(wa[o * CFULL + k]);
}

// ---------------------------------------------------------------------------
// Kernel 1: adaptive max pool of channels 256..511 to 2x2
// ---------------------------------------------------------------------------
__global__ __launch_bounds__(256) void pool_kernel(const float* __restrict__ x) {
    int blk = blockIdx.x;
    int q  = blk & 3;
    int cc = (blk >> 2) & 255;
    int b  = blk >> 10;
    int qh = q >> 1, qw = q & 1;
    const float* xin = x + ((size_t)(b * CFULL + 256 + cc)) * HW + qh * 64 * WW + qw * 64;
    const float4* xin4 = reinterpret_cast<const float4*>(xin);

    float m = -INFINITY;
    for (int i = threadIdx.x; i < 1024; i += 256) {
        int r = i >> 4, c4 = i & 15;
        float4 v = xin4[r * 32 + c4];
        m = fmaxf(m, fmaxf(fmaxf(v.x, v.y), fmaxf(v.z, v.w)));
    }
    __shared__ float red[256];
    red[threadIdx.x] = m;
    __syncthreads();
    for (int s = 128; s > 0; s >>= 1) {
        if (threadIdx.x < s) red[threadIdx.x] = fmaxf(red[threadIdx.x], red[threadIdx.x + s]);
        __syncthreads();
    }
    if (threadIdx.x == 0) g_pool[(b * HC + cc) * 4 + q] = red[0];
}

// ---------------------------------------------------------------------------
// Kernel 2: tiny 2x2 dwconvs + base[b][q][o]
// ---------------------------------------------------------------------------
__global__ __launch_bounds__(512) void base_kernel(
    const float* __restrict__ w2, const float* __restrict__ b2,
    const float* __restrict__ w3, const float* __restrict__ b3,
    const float* __restrict__ w4, const float* __restrict__ b4,
    const float* __restrict__ wa, const float* __restrict__ ba)
{
    int b  = blockIdx.x >> 2;
    int oc = (blockIdx.x & 3) * 128;
    __shared__ float catlow[256][4];
    int t = threadIdx.x;
    if (t < 256) {
        const float* wp;
        float bias;
        if (t < 128)       { wp = w2 + t * 9;         bias = b2[t];        }
        else if (t < 192)  { wp = w3 + (t - 128) * 9; bias = b3[t - 128]; }
        else               { wp = w4 + (t - 192) * 9; bias = b4[t - 192]; }
        float i00 = g_pool[(b * HC + t) * 4 + 0];
        float i01 = g_pool[(b * HC + t) * 4 + 1];
        float i10 = g_pool[(b * HC + t) * 4 + 2];
        float i11 = g_pool[(b * HC + t) * 4 + 3];
        catlow[t][0] = i00*wp[4] + i01*wp[5] + i10*wp[7] + i11*wp[8] + bias;
        catlow[t][1] = i00*wp[3] + i01*wp[4] + i10*wp[6] + i11*wp[7] + bias;
        catlow[t][2] = i00*wp[1] + i01*wp[2] + i10*wp[4] + i11*wp[5] + bias;
        catlow[t][3] = i00*wp[0] + i01*wp[1] + i10*wp[3] + i11*wp[4] + bias;
    }
    __syncthreads();
    int o    = oc + (t >> 2);
    int part = t & 3;
    int cc0  = part * 64;
    float a0 = 0.f, a1 = 0.f, a2 = 0.f, a3 = 0.f;
    #pragma unroll 4
    for (int cc = cc0; cc < cc0 + 64; ++cc) {
        float wv = wa[o * CFULL + 256 + cc];
        a0 = fmaf(wv, catlow[cc][0], a0);
        a1 = fmaf(wv, catlow[cc][1], a1);
        a2 = fmaf(wv, catlow[cc][2], a2);
        a3 = fmaf(wv, catlow[cc][3], a3);
    }
    #pragma unroll
    for (int off = 1; off < 4; off <<= 1) {
        a0 += __shfl_xor_sync(0xffffffff, a0, off);
        a1 += __shfl_xor_sync(0xffffffff, a1, off);
        a2 += __shfl_xor_sync(0xffffffff, a2, off);
        a3 += __shfl_xor_sync(0xffffffff, a3, off);
    }
    if (part == 0) {
        float bav = ba[o];
        g_base[(b * 4 + 0) * CFULL + o] = a0 + bav;
        g_base[(b * 4 + 1) * CFULL + o] = a1 + bav;
        g_base[(b * 4 + 2) * CFULL + o] = a2 + bav;
        g_base[(b * 4 + 3) * CFULL + o] = a3 + bav;
    }
}

// ---------------------------------------------------------------------------
// Kernel 3: dwconv3x3 + transpose -> g_x1t[b][p][k] (fp16).
// grid = (b, row, seg of 2 channel-chunks): 4x parallelism vs R10.
// ---------------------------------------------------------------------------
#define STW 137
#define DW_SMEM_BYTES (32 * 3 * STW * 4)   // 52,608

__global__ __launch_bounds__(256) void dwconvT_kernel(
    const float* __restrict__ x, const float* __restrict__ w1, const float* __restrict__ b1)
{
    extern __shared__ float stage[];   // [32 ch][3 rr][STW]
    int blk = blockIdx.x;
    int seg = blk & 3;
    int row = (blk >> 2) & 127;
    int b   = blk >> 9;
    int tid = threadIdx.x;
    int kl = tid & 31;
    int ng = tid >> 5;
    int c0 = ng * 16;

    if (tid < 96) {
        int ch = tid / 3, rr = tid - 3 * ch;
        stage[ch * (3 * STW) + rr * STW + 3]   = 0.f;
        stage[ch * (3 * STW) + rr * STW + 132] = 0.f;
    }

    __half* outbase = g_x1t + ((size_t)b * HW + (size_t)row * WW) * HC;

    for (int cc = seg * 2; cc < seg * 2 + 2; ++cc) {
        __syncthreads();
        #pragma unroll
        for (int j = 0; j < 12; ++j) {
            int i = tid + 256 * j;
            int c4 = i & 31;
            int g3 = i >> 5;
            int ch = g3 / 3;
            int rr = g3 - 3 * ch;
            int gr = row + rr - 1;
            float4 v = make_float4(0.f, 0.f, 0.f, 0.f);
            if (gr >= 0 && gr < HH)
                v = *reinterpret_cast<const float4*>(
                    x + ((size_t)(b * CFULL + cc * 32 + ch)) * HW + gr * WW + c4 * 4);
            float* sp = stage + ch * (3 * STW) + rr * STW + 4 + c4 * 4;
            sp[0] = v.x; sp[1] = v.y; sp[2] = v.z; sp[3] = v.w;
        }
        __syncthreads();
        int k = cc * 32 + kl;
        const float* wp = w1 + k * 9;
        float w00 = wp[0], w01 = wp[1], w02 = wp[2];
        float w10 = wp[3], w11 = wp[4], w12 = wp[5];
        float w20 = wp[6], w21 = wp[7], w22 = wp[8];
        float bias = b1[k];

        float rv[3][18];
        const float* sb = stage + kl * (3 * STW);
        #pragma unroll
        for (int rr = 0; rr < 3; ++rr) {
            #pragma unroll
            for (int i = 0; i < 18; ++i)
                rv[rr][i] = sb[rr * STW + 3 + c0 + i];
        }
        #pragma unroll
        for (int c = 0; c < 16; ++c) {
            float acc = bias;
            acc = fmaf(w00, rv[0][c],     acc);
            acc = fmaf(w01, rv[0][c + 1], acc);
            acc = fmaf(w02, rv[0][c + 2], acc);
            acc = fmaf(w10, rv[1][c],     acc);
            acc = fmaf(w11, rv[1][c + 1], acc);
            acc = fmaf(w12, rv[1][c + 2], acc);
            acc = fmaf(w20, rv[2][c],     acc);
            acc = fmaf(w21, rv[2][c + 1], acc);
            acc = fmaf(w22, rv[2][c + 2], acc);
            outbase[(size_t)(c0 + c) * HC + k] = __float2half_rn(acc);
        }
    }
}

// ---------------------------------------------------------------------------
// Kernel 4: fp16 GEMM (m16n8k16, full ldmatrix, cp.async double buffer,
// BK=64: 4 mainloop iterations), fp32 accumulate, direct epilogue.
// A = g_wa_h[m][k], B = g_x1t[n][k], both K-major fp16. D = A * B^T.
// ---------------------------------------------------------------------------
__device__ __forceinline__ float gelu_exact(float v) {
    return 0.5f * v * (1.0f + erff(v * 0.70710678118654752f));
}
__device__ __forceinline__ void mma_f16(float (&d)[4], const uint32_t (&a)[4],
                                        uint32_t b0, uint32_t b1) {
    asm volatile(
        "mma.sync.aligned.m16n8k16.row.col.f32.f16.f16.f32 "
        "{%0,%1,%2,%3}, {%4,%5,%6,%7}, {%8,%9}, {%0,%1,%2,%3};"
        : "+f"(d[0]), "+f"(d[1]), "+f"(d[2]), "+f"(d[3])
        : "r"(a[0]), "r"(a[1]), "r"(a[2]), "r"(a[3]), "r"(b0), "r"(b1));
}
__device__ __forceinline__ void cp_async16(uint32_t dst, const void* src) {
    asm volatile("cp.async.cg.shared.global [%0], [%1], 16;" :: "r"(dst), "l"(src));
}
__device__ __forceinline__ void ldsm4(uint32_t (&r)[4], uint32_t addr) {
    asm volatile("ldmatrix.sync.aligned.m8n8.x4.shared.b16 {%0,%1,%2,%3}, [%4];"
                 : "=r"(r[0]), "=r"(r[1]), "=r"(r[2]), "=r"(r[3]) : "r"(addr));
}

#define BM 128
#define BN 128
#define BK 64
#define HSTR 72                            // halves per smem row (144B: conflict-free)
#define TIL_H (128 * HSTR)                 // halves per tile per stage = 9216
#define GEMM_SMEM_BYTES (4 * TIL_H * 2)    // 73,728

__global__ __launch_bounds__(256, 2) void gemm_gelu_kernel(
    const float* __restrict__ x, float* __restrict__ out)
{
    extern __shared__ __half hsm[];
    // layout: As [2][128][HSTR] halves, then Bs [2][128][HSTR]
    uint32_t as_base = (uint32_t)__cvta_generic_to_shared(hsm);
    uint32_t bs_base = as_base + 2 * TIL_H * 2;

    int m0 = blockIdx.x * BM;              // m-block fastest: B-tile L2 reuse
    int bx = blockIdx.y;                   // image row; n0 = bx*128
    int b  = blockIdx.z;
    int tid = threadIdx.x;
    int lane = tid & 31, warp = tid >> 5;
    int warpM = warp & 3;
    int warpN = warp >> 2;

    const __half* x1b = g_x1t + ((size_t)b * HW + (size_t)bx * WW) * HC;  // [n][256]
    int n0 = bx * BN;

    // cp.async: 128 rows x 8 chunks (8 halves) per tile = 1024 chunks, 4/thread
    int rowi[4], kci[4];
    #pragma unroll
    for (int j = 0; j < 4; ++j) {
        int idx = tid + 256 * j;
        rowi[j] = idx >> 3;
        kci[j]  = (idx & 7) * 8;
    }

    auto load_stage = [&](int k0, int s) {
        #pragma unroll
        for (int j = 0; j < 4; ++j) {
            const __half* srcA = g_wa_h + (size_t)(m0 + rowi[j]) * HC + k0 + kci[j];
            uint32_t dstA = as_base + (s * TIL_H + rowi[j] * HSTR + kci[j]) * 2;
            cp_async16(dstA, srcA);
            const __half* srcB = x1b + (size_t)rowi[j] * HC + k0 + kci[j];
            uint32_t dstB = bs_base + (s * TIL_H + rowi[j] * HSTR + kci[j]) * 2;
            cp_async16(dstB, srcB);
        }
        asm volatile("cp.async.commit_group;" ::: "memory");
    };

    // ldmatrix per-lane offsets (halves)
    int j4 = lane >> 3;
    int a_row = ((j4 & 1) * 8) + (lane & 7);
    int a_kc  = (j4 >> 1) * 8;
    int b_row = ((j4 >> 1) * 8) + (lane & 7);
    int b_kc  = (j4 & 1) * 8;
    int aoff0 = (warpM * 32 +  0 + a_row) * HSTR + a_kc;
    int aoff1 = (warpM * 32 + 16 + a_row) * HSTR + a_kc;
    int boff[4];
    #pragma unroll
    for (int ntp = 0; ntp < 4; ++ntp)
        boff[ntp] = (warpN * 64 + ntp * 16 + b_row) * HSTR + b_kc;

    float acc[2][8][4] = {};

    load_stage(0, 0);

    #pragma unroll 1
    for (int it = 0; it < HC / BK; ++it) {
        asm volatile("cp.async.wait_group 0;" ::: "memory");
        __syncthreads();
        if (it < HC / BK - 1) load_stage((it + 1) * BK, (it + 1) & 1);

        int s = it & 1;
        uint32_t aB = as_base + s * TIL_H * 2;
        uint32_t bB = bs_base + s * TIL_H * 2;

        #pragma unroll
        for (int ks = 0; ks < 4; ++ks) {        // four k16 steps per BK=64
            uint32_t af[2][4];
            ldsm4(af[0], aB + (aoff0 + ks * 16) * 2);
            ldsm4(af[1], aB + (aoff1 + ks * 16) * 2);
            #pragma unroll
            for (int ntp = 0; ntp < 4; ++ntp) {
                uint32_t bb[4];
                ldsm4(bb, bB + (boff[ntp] + ks * 16) * 2);
                mma_f16(acc[0][2 * ntp    ], af[0], bb[0], bb[1]);
                mma_f16(acc[1][2 * ntp    ], af[1], bb[0], bb[1]);
                mma_f16(acc[0][2 * ntp + 1], af[0], bb[2], bb[3]);
                mma_f16(acc[1][2 * ntp + 1], af[1], bb[2], bb[3]);
            }
        }
    }

    // Epilogue (direct): +base, exact GELU, gate by x, store.
    int q = ((bx >= 64) ? 2 : 0) + warpN;
    const float* basep = g_base + (b * 4 + q) * CFULL;

    #pragma unroll
    for (int mt = 0; mt < 2; ++mt) {
        int mrow0 = m0 + warpM * 32 + mt * 16 + (lane >> 2);
        int mrow1 = mrow0 + 8;
        float bs0 = basep[mrow0];
        float bs1 = basep[mrow1];
        #pragma unroll
        for (int nt = 0; nt < 8; ++nt) {
            int n = n0 + warpN * 64 + nt * 8 + (lane & 3) * 2;
            size_t off0 = ((size_t)(b * CFULL + mrow0)) * HW + n;
            size_t off1 = ((size_t)(b * CFULL + mrow1)) * HW + n;
            float2 xv0 = *reinterpret_cast<const float2*>(x + off0);
            float2 xv1 = *reinterpret_cast<const float2*>(x + off1);
            float2 r0, r1;
            r0.x = gelu_exact(acc[mt][nt][0] + bs0) * xv0.x;
            r0.y = gelu_exact(acc[mt][nt][1] + bs0) * xv0.y;
            r1.x = gelu_exact(acc[mt][nt][2] + bs1) * xv1.x;
            r1.y = gelu_exact(acc[mt][nt][3] + bs1) * xv1.y;
            *reinterpret_cast<float2*>(out + off0) = r0;
            *reinterpret_cast<float2*>(out + off1) = r1;
        }
    }
}

// ---------------------------------------------------------------------------
extern "C" void kernel_launch(void* const* d_in, const int* in_sizes, int n_in,
                              void* d_out, int out_size) {
    const float* x  = (const float*)d_in[0];
    const float* w1 = (const float*)d_in[1];
    const float* b1 = (const float*)d_in[2];
    const float* w2 = (const float*)d_in[3];
    const float* b2 = (const float*)d_in[4];
    const float* w3 = (const float*)d_in[5];
    const float* b3 = (const float*)d_in[6];
    const float* w4 = (const float*)d_in[7];
    const float* b4 = (const float*)d_in[8];
    const float* wa = (const float*)d_in[9];
    const float* ba = (const float*)d_in[10];
    float* out = (float*)d_out;

    cudaFuncSetAttribute(dwconvT_kernel,
                         cudaFuncAttributeMaxDynamicSharedMemorySize, DW_SMEM_BYTES);
    cudaFuncSetAttribute(gemm_gelu_kernel,
                         cudaFuncAttributeMaxDynamicSharedMemorySize, GEMM_SMEM_BYTES);

    // Fork-join: waconv+pool+base on a side stream, dwconvT on the main
    // (captured) stream, join before the gemm.
    cudaStream_t side;
    cudaStreamCreateWithFlags(&side, cudaStreamNonBlocking);
    cudaEvent_t eFork, eJoin;
    cudaEventCreateWithFlags(&eFork, cudaEventDisableTiming);
    cudaEventCreateWithFlags(&eJoin, cudaEventDisableTiming);

    cudaEventRecord(eFork, 0);
    cudaStreamWaitEvent(side, eFork, 0);

    waconv_kernel<<<512, 256, 0, side>>>(wa);
    pool_kernel<<<BATCH * HC * 4, 256, 0, side>>>(x);
    base_kernel<<<16, 512, 0, side>>>(w2, b2, w3, b3, w4, b4, wa, ba);
    cudaEventRecord(eJoin, side);

    dwconvT_kernel<<<BATCH * HH * 4, 256, DW_SMEM_BYTES>>>(x, w1, b1);

    cudaStreamWaitEvent(0, eJoin, 0);
    gemm_gelu_kernel<<<dim3(CFULL / BM, HH, BATCH), 256, GEMM_SMEM_BYTES>>>(x, out);
}

// round 12
// speedup vs baseline: 1.0825x; 1.0825x over previous
#include <cuda_runtime.h>
#include <cuda_fp16.h>
#include <math.h>
#include <stdint.h>

#define BATCH 4
#define CFULL 512
#define HC 256
#define HH 128
#define WW 128
#define HW (HH*WW)

// x1 transposed + fp16: [b][p(pixel)][k(channel)], k contiguous
__device__ __align__(16) __half g_x1t[BATCH * HW * HC];
__device__ __align__(16) __half g_wa_h[CFULL * HC];   // wa[:, 0:256] in fp16
__device__ float g_pool[BATCH * HC * 4];
__device__ float g_base[BATCH * 4 * CFULL];

// ---------------------------------------------------------------------------
// Kernel 0: convert wa[:, 0:256] to fp16
// ---------------------------------------------------------------------------
__global__ __launch_bounds__(256) void waconv_kernel(const float* __restrict__ wa) {
    int i = blockIdx.x * 256 + threadIdx.x;     // 512*256 = 131072
    int o = i >> 8, k = i & 255;
    g_wa_h[i] = __float2half_rn(wa[o * CFULL + k]);
}

// ---------------------------------------------------------------------------
// Kernel 1: adaptive max pool of channels 256..511 to 2x2
// ---------------------------------------------------------------------------
__global__ __launch_bounds__(256) void pool_kernel(const float* __restrict__ x) {
    int blk = blockIdx.x;
    int q  = blk & 3;
    int cc = (blk >> 2) & 255;
    int b  = blk >> 10;
    int qh = q >> 1, qw = q & 1;
    const float* xin = x + ((size_t)(b * CFULL + 256 + cc)) * HW + qh * 64 * WW + qw * 64;
    const float4* xin4 = reinterpret_cast<const float4*>(xin);

    float m = -INFINITY;
    for (int i = threadIdx.x; i < 1024; i += 256) {
        int r = i >> 4, c4 = i & 15;
        float4 v = xin4[r * 32 + c4];
        m = fmaxf(m, fmaxf(fmaxf(v.x, v.y), fmaxf(v.z, v.w)));
    }
    __shared__ float red[256];
    red[threadIdx.x] = m;
    __syncthreads();
    for (int s = 128; s > 0; s >>= 1) {
        if (threadIdx.x < s) red[threadIdx.x] = fmaxf(red[threadIdx.x], red[threadIdx.x + s]);
        __syncthreads();
    }
    if (threadIdx.x == 0) g_pool[(b * HC + cc) * 4 + q] = red[0];
}

// ---------------------------------------------------------------------------
// Kernel 2: tiny 2x2 dwconvs + base[b][q][o]
// ---------------------------------------------------------------------------
__global__ __launch_bounds__(512) void base_kernel(
    const float* __restrict__ w2, const float* __restrict__ b2,
    const float* __restrict__ w3, const float* __restrict__ b3,
    const float* __restrict__ w4, const float* __restrict__ b4,
    const float* __restrict__ wa, const float* __restrict__ ba)
{
    int b  = blockIdx.x >> 2;
    int oc = (blockIdx.x & 3) * 128;
    __shared__ float catlow[256][4];
    int t = threadIdx.x;
    if (t < 256) {
        const float* wp;
        float bias;
        if (t < 128)       { wp = w2 + t * 9;         bias = b2[t];        }
        else if (t < 192)  { wp = w3 + (t - 128) * 9; bias = b3[t - 128]; }
        else               { wp = w4 + (t - 192) * 9; bias = b4[t - 192]; }
        float i00 = g_pool[(b * HC + t) * 4 + 0];
        float i01 = g_pool[(b * HC + t) * 4 + 1];
        float i10 = g_pool[(b * HC + t) * 4 + 2];
        float i11 = g_pool[(b * HC + t) * 4 + 3];
        catlow[t][0] = i00*wp[4] + i01*wp[5] + i10*wp[7] + i11*wp[8] + bias;
        catlow[t][1] = i00*wp[3] + i01*wp[4] + i10*wp[6] + i11*wp[7] + bias;
        catlow[t][2] = i00*wp[1] + i01*wp[2] + i10*wp[4] + i11*wp[5] + bias;
        catlow[t][3] = i00*wp[0] + i01*wp[1] + i10*wp[3] + i11*wp[4] + bias;
    }
    __syncthreads();
    int o    = oc + (t >> 2);
    int part = t & 3;
    int cc0  = part * 64;
    float a0 = 0.f, a1 = 0.f, a2 = 0.f, a3 = 0.f;
    #pragma unroll 4
    for (int cc = cc0; cc < cc0 + 64; ++cc) {
        float wv = wa[o * CFULL + 256 + cc];
        a0 = fmaf(wv, catlow[cc][0], a0);
        a1 = fmaf(wv, catlow[cc][1], a1);
        a2 = fmaf(wv, catlow[cc][2], a2);
        a3 = fmaf(wv, catlow[cc][3], a3);
    }
    #pragma unroll
    for (int off = 1; off < 4; off <<= 1) {
        a0 += __shfl_xor_sync(0xffffffff, a0, off);
        a1 += __shfl_xor_sync(0xffffffff, a1, off);
        a2 += __shfl_xor_sync(0xffffffff, a2, off);
        a3 += __shfl_xor_sync(0xffffffff, a3, off);
    }
    if (part == 0) {
        float bav = ba[o];
        g_base[(b * 4 + 0) * CFULL + o] = a0 + bav;
        g_base[(b * 4 + 1) * CFULL + o] = a1 + bav;
        g_base[(b * 4 + 2) * CFULL + o] = a2 + bav;
        g_base[(b * 4 + 3) * CFULL + o] = a3 + bav;
    }
}

// ---------------------------------------------------------------------------
// Kernel 3: dwconv3x3 + transpose -> g_x1t[b][p][k] (fp16).
// grid = (b, row, seg of 2 channel-chunks); chunk loop kept ROLLED
// (#pragma unroll 1) so regs stay ~80 and 4 CTAs/SM co-reside.
// ---------------------------------------------------------------------------
#define STW 137
#define DW_SMEM_BYTES (32 * 3 * STW * 4)   // 52,608

__global__ __launch_bounds__(256) void dwconvT_kernel(
    const float* __restrict__ x, const float* __restrict__ w1, const float* __restrict__ b1)
{
    extern __shared__ float stage[];   // [32 ch][3 rr][STW]
    int blk = blockIdx.x;
    int seg = blk & 3;
    int row = (blk >> 2) & 127;
    int b   = blk >> 9;
    int tid = threadIdx.x;
    int kl = tid & 31;
    int ng = tid >> 5;
    int c0 = ng * 16;

    if (tid < 96) {
        int ch = tid / 3, rr = tid - 3 * ch;
        stage[ch * (3 * STW) + rr * STW + 3]   = 0.f;
        stage[ch * (3 * STW) + rr * STW + 132] = 0.f;
    }

    __half* outbase = g_x1t + ((size_t)b * HW + (size_t)row * WW) * HC;

    #pragma unroll 1
    for (int cc = seg * 2; cc < seg * 2 + 2; ++cc) {
        __syncthreads();
        #pragma unroll
        for (int j = 0; j < 12; ++j) {
            int i = tid + 256 * j;
            int c4 = i & 31;
            int g3 = i >> 5;
            int ch = g3 / 3;
            int rr = g3 - 3 * ch;
            int gr = row + rr - 1;
            float4 v = make_float4(0.f, 0.f, 0.f, 0.f);
            if (gr >= 0 && gr < HH)
                v = *reinterpret_cast<const float4*>(
                    x + ((size_t)(b * CFULL + cc * 32 + ch)) * HW + gr * WW + c4 * 4);
            float* sp = stage + ch * (3 * STW) + rr * STW + 4 + c4 * 4;
            sp[0] = v.x; sp[1] = v.y; sp[2] = v.z; sp[3] = v.w;
        }
        __syncthreads();
        int k = cc * 32 + kl;
        const float* wp = w1 + k * 9;
        float w00 = wp[0], w01 = wp[1], w02 = wp[2];
        float w10 = wp[3], w11 = wp[4], w12 = wp[5];
        float w20 = wp[6], w21 = wp[7], w22 = wp[8];
        float bias = b1[k];

        float rv[3][18];
        const float* sb = stage + kl * (3 * STW);
        #pragma unroll
        for (int rr = 0; rr < 3; ++rr) {
            #pragma unroll
            for (int i = 0; i < 18; ++i)
                rv[rr][i] = sb[rr * STW + 3 + c0 + i];
        }
        #pragma unroll
        for (int c = 0; c < 16; ++c) {
            float acc = bias;
            acc = fmaf(w00, rv[0][c],     acc);
            acc = fmaf(w01, rv[0][c + 1], acc);
            acc = fmaf(w02, rv[0][c + 2], acc);
            acc = fmaf(w10, rv[1][c],     acc);
            acc = fmaf(w11, rv[1][c + 1], acc);
            acc = fmaf(w12, rv[1][c + 2], acc);
            acc = fmaf(w20, rv[2][c],     acc);
            acc = fmaf(w21, rv[2][c + 1], acc);
            acc = fmaf(w22, rv[2][c + 2], acc);
            outbase[(size_t)(c0 + c) * HC + k] = __float2half_rn(acc);
        }
    }
}

// ---------------------------------------------------------------------------
// Kernel 4: fp16 GEMM (m16n8k16, full ldmatrix, cp.async double buffer,
// BK=32 — R10's measured-best config), fp32 accumulate, direct epilogue.
// A = g_wa_h[m][k], B = g_x1t[n][k], both K-major fp16. D = A * B^T.
// ---------------------------------------------------------------------------
__device__ __forceinline__ float gelu_exact(float v) {
    return 0.5f * v * (1.0f + erff(v * 0.70710678118654752f));
}
__device__ __forceinline__ void mma_f16(float (&d)[4], const uint32_t (&a)[4],
                                        uint32_t b0, uint32_t b1) {
    asm volatile(
        "mma.sync.aligned.m16n8k16.row.col.f32.f16.f16.f32 "
        "{%0,%1,%2,%3}, {%4,%5,%6,%7}, {%8,%9}, {%0,%1,%2,%3};"
        : "+f"(d[0]), "+f"(d[1]), "+f"(d[2]), "+f"(d[3])
        : "r"(a[0]), "r"(a[1]), "r"(a[2]), "r"(a[3]), "r"(b0), "r"(b1));
}
__device__ __forceinline__ void cp_async16(uint32_t dst, const void* src) {
    asm volatile("cp.async.cg.shared.global [%0], [%1], 16;" :: "r"(dst), "l"(src));
}
__device__ __forceinline__ void ldsm4(uint32_t (&r)[4], uint32_t addr) {
    asm volatile("ldmatrix.sync.aligned.m8n8.x4.shared.b16 {%0,%1,%2,%3}, [%4];"
                 : "=r"(r[0]), "=r"(r[1]), "=r"(r[2]), "=r"(r[3]) : "r"(addr));
}

#define BM 128
#define BN 128
#define BK 32
#define HSTR 40                            // halves per smem row (80B: conflict-free)
#define TIL_H (128 * HSTR)                 // halves per tile per stage = 5120
#define GEMM_SMEM_BYTES (4 * TIL_H * 2)    // 40,960

__global__ __launch_bounds__(256, 2) void gemm_gelu_kernel(
    const float* __restrict__ x, float* __restrict__ out)
{
    extern __shared__ __half hsm[];
    // layout: As [2][128][HSTR] halves, then Bs [2][128][HSTR]
    uint32_t as_base = (uint32_t)__cvta_generic_to_shared(hsm);
    uint32_t bs_base = as_base + 2 * TIL_H * 2;

    int m0 = blockIdx.x * BM;              // m-block fastest: B-tile L2 reuse
    int bx = blockIdx.y;                   // image row; n0 = bx*128
    int b  = blockIdx.z;
    int tid = threadIdx.x;
    int lane = tid & 31, warp = tid >> 5;
    int warpM = warp & 3;
    int warpN = warp >> 2;

    const __half* x1b = g_x1t + ((size_t)b * HW + (size_t)bx * WW) * HC;  // [n][256]
    int n0 = bx * BN;

    // cp.async: 128 rows x 4 chunks (8 halves) per tile = 512 chunks, 2/thread
    int rowi[2], kci[2];
    #pragma unroll
    for (int j = 0; j < 2; ++j) {
        int idx = tid + 256 * j;
        rowi[j] = idx >> 2;
        kci[j]  = (idx & 3) * 8;
    }

    auto load_stage = [&](int k0, int s) {
        #pragma unroll
        for (int j = 0; j < 2; ++j) {
            const __half* srcA = g_wa_h + (size_t)(m0 + rowi[j]) * HC + k0 + kci[j];
            uint32_t dstA = as_base + (s * TIL_H + rowi[j] * HSTR + kci[j]) * 2;
            cp_async16(dstA, srcA);
            const __half* srcB = x1b + (size_t)rowi[j] * HC + k0 + kci[j];
            uint32_t dstB = bs_base + (s * TIL_H + rowi[j] * HSTR + kci[j]) * 2;
            cp_async16(dstB, srcB);
        }
        asm volatile("cp.async.commit_group;" ::: "memory");
    };

    // ldmatrix per-lane offsets (halves)
    int j4 = lane >> 3;
    int a_row = ((j4 & 1) * 8) + (lane & 7);
    int a_kc  = (j4 >> 1) * 8;
    int b_row = ((j4 >> 1) * 8) + (lane & 7);
    int b_kc  = (j4 & 1) * 8;
    int aoff0 = (warpM * 32 +  0 + a_row) * HSTR + a_kc;
    int aoff1 = (warpM * 32 + 16 + a_row) * HSTR + a_kc;
    int boff[4];
    #pragma unroll
    for (int ntp = 0; ntp < 4; ++ntp)
        boff[ntp] = (warpN * 64 + ntp * 16 + b_row) * HSTR + b_kc;

    float acc[2][8][4] = {};

    load_stage(0, 0);

    #pragma unroll 1
    for (int it = 0; it < HC / BK; ++it) {
        asm volatile("cp.async.wait_group 0;" ::: "memory");
        __syncthreads();
        if (it < HC / BK - 1) load_stage((it + 1) * BK, (it + 1) & 1);

        int s = it & 1;
        uint32_t aB = as_base + s * TIL_H * 2;
        uint32_t bB = bs_base + s * TIL_H * 2;

        #pragma unroll
        for (int ks = 0; ks < 2; ++ks) {        // two k16 steps per BK=32
            uint32_t af[2][4];
            ldsm4(af[0], aB + (aoff0 + ks * 16) * 2);
            ldsm4(af[1], aB + (aoff1 + ks * 16) * 2);
            #pragma unroll
            for (int ntp = 0; ntp < 4; ++ntp) {
                uint32_t bb[4];
                ldsm4(bb, bB + (boff[ntp] + ks * 16) * 2);
                mma_f16(acc[0][2 * ntp    ], af[0], bb[0], bb[1]);
                mma_f16(acc[1][2 * ntp    ], af[1], bb[0], bb[1]);
                mma_f16(acc[0][2 * ntp + 1], af[0], bb[2], bb[3]);
                mma_f16(acc[1][2 * ntp + 1], af[1], bb[2], bb[3]);
            }
        }
    }

    // Epilogue (direct): +base, exact GELU, gate by x, store.
    int q = ((bx >= 64) ? 2 : 0) + warpN;
    const float* basep = g_base + (b * 4 + q) * CFULL;

    #pragma unroll
    for (int mt = 0; mt < 2; ++mt) {
        int mrow0 = m0 + warpM * 32 + mt * 16 + (lane >> 2);
        int mrow1 = mrow0 + 8;
        float bs0 = basep[mrow0];
        float bs1 = basep[mrow1];
        #pragma unroll
        for (int nt = 0; nt < 8; ++nt) {
            int n = n0 + warpN * 64 + nt * 8 + (lane & 3) * 2;
            size_t off0 = ((size_t)(b * CFULL + mrow0)) * HW + n;
            size_t off1 = ((size_t)(b * CFULL + mrow1)) * HW + n;
            float2 xv0 = *reinterpret_cast<const float2*>(x + off0);
            float2 xv1 = *reinterpret_cast<const float2*>(x + off1);
            float2 r0, r1;
            r0.x = gelu_exact(acc[mt][nt][0] + bs0) * xv0.x;
            r0.y = gelu_exact(acc[mt][nt][1] + bs0) * xv0.y;
            r1.x = gelu_exact(acc[mt][nt][2] + bs1) * xv1.x;
            r1.y = gelu_exact(acc[mt][nt][3] + bs1) * xv1.y;
            *reinterpret_cast<float2*>(out + off0) = r0;
            *reinterpret_cast<float2*>(out + off1) = r1;
        }
    }
}

// ---------------------------------------------------------------------------
extern "C" void kernel_launch(void* const* d_in, const int* in_sizes, int n_in,
                              void* d_out, int out_size) {
    const float* x  = (const float*)d_in[0];
    const float* w1 = (const float*)d_in[1];
    const float* b1 = (const float*)d_in[2];
    const float* w2 = (const float*)d_in[3];
    const float* b2 = (const float*)d_in[4];
    const float* w3 = (const float*)d_in[5];
    const float* b3 = (const float*)d_in[6];
    const float* w4 = (const float*)d_in[7];
    const float* b4 = (const float*)d_in[8];
    const float* wa = (const float*)d_in[9];
    const float* ba = (const float*)d_in[10];
    float* out = (float*)d_out;

    cudaFuncSetAttribute(dwconvT_kernel,
                         cudaFuncAttributeMaxDynamicSharedMemorySize, DW_SMEM_BYTES);
    cudaFuncSetAttribute(gemm_gelu_kernel,
                         cudaFuncAttributeMaxDynamicSharedMemorySize, GEMM_SMEM_BYTES);

    // Fork-join: waconv+pool+base on a side stream, dwconvT on the main
    // (captured) stream, join before the gemm.
    cudaStream_t side;
    cudaStreamCreateWithFlags(&side, cudaStreamNonBlocking);
    cudaEvent_t eFork, eJoin;
    cudaEventCreateWithFlags(&eFork, cudaEventDisableTiming);
    cudaEventCreateWithFlags(&eJoin, cudaEventDisableTiming);

    cudaEventRecord(eFork, 0);
    cudaStreamWaitEvent(side, eFork, 0);

    waconv_kernel<<<512, 256, 0, side>>>(wa);
    pool_kernel<<<BATCH * HC * 4, 256, 0, side>>>(x);
    base_kernel<<<16, 512, 0, side>>>(w2, b2, w3, b3, w4, b4, wa, ba);
    cudaEventRecord(eJoin, side);

    dwconvT_kernel<<<BATCH * HH * 4, 256, DW_SMEM_BYTES>>>(x, w1, b1);

    cudaStreamWaitEvent(0, eJoin, 0);
    gemm_gelu_kernel<<<dim3(CFULL / BM, HH, BATCH), 256, GEMM_SMEM_BYTES>>>(x, out);
}

// round 13
// speedup vs baseline: 1.2184x; 1.1255x over previous
#include <cuda_runtime.h>
#include <cuda_fp16.h>
#include <math.h>
#include <stdint.h>

#define BATCH 4
#define CFULL 512
#define HC 256
#define HH 128
#define WW 128
#define HW (HH*WW)

// x1 transposed + fp16: [b][p(pixel)][k(channel)], k contiguous
__device__ __align__(16) __half g_x1t[BATCH * HW * HC];
__device__ __align__(16) __half g_wa_h[CFULL * HC];   // wa[:, 0:256] in fp16
__device__ float g_pool[BATCH * HC * 4];
__device__ float g_base[BATCH * 4 * CFULL];

// ---------------------------------------------------------------------------
// Kernel 0: convert wa[:, 0:256] to fp16
// ---------------------------------------------------------------------------
__global__ __launch_bounds__(256) void waconv_kernel(const float* __restrict__ wa) {
    int i = blockIdx.x * 256 + threadIdx.x;     // 512*256 = 131072
    int o = i >> 8, k = i & 255;
    g_wa_h[i] = __float2half_rn(wa[o * CFULL + k]);
}

// ---------------------------------------------------------------------------
// Kernel 1: adaptive max pool of channels 256..511 to 2x2
// ---------------------------------------------------------------------------
__global__ __launch_bounds__(256) void pool_kernel(const float* __restrict__ x) {
    int blk = blockIdx.x;
    int q  = blk & 3;
    int cc = (blk >> 2) & 255;
    int b  = blk >> 10;
    int qh = q >> 1, qw = q & 1;
    const float* xin = x + ((size_t)(b * CFULL + 256 + cc)) * HW + qh * 64 * WW + qw * 64;
    const float4* xin4 = reinterpret_cast<const float4*>(xin);

    float m = -INFINITY;
    for (int i = threadIdx.x; i < 1024; i += 256) {
        int r = i >> 4, c4 = i & 15;
        float4 v = xin4[r * 32 + c4];
        m = fmaxf(m, fmaxf(fmaxf(v.x, v.y), fmaxf(v.z, v.w)));
    }
    __shared__ float red[256];
    red[threadIdx.x] = m;
    __syncthreads();
    for (int s = 128; s > 0; s >>= 1) {
        if (threadIdx.x < s) red[threadIdx.x] = fmaxf(red[threadIdx.x], red[threadIdx.x + s]);
        __syncthreads();
    }
    if (threadIdx.x == 0) g_pool[(b * HC + cc) * 4 + q] = red[0];
}

// ---------------------------------------------------------------------------
// Kernel 2: tiny 2x2 dwconvs + base[b][q][o]
// ---------------------------------------------------------------------------
__global__ __launch_bounds__(512) void base_kernel(
    const float* __restrict__ w2, const float* __restrict__ b2,
    const float* __restrict__ w3, const float* __restrict__ b3,
    const float* __restrict__ w4, const float* __restrict__ b4,
    const float* __restrict__ wa, const float* __restrict__ ba)
{
    int b  = blockIdx.x >> 2;
    int oc = (blockIdx.x & 3) * 128;
    __shared__ float catlow[256][4];
    int t = threadIdx.x;
    if (t < 256) {
        const float* wp;
        float bias;
        if (t < 128)       { wp = w2 + t * 9;         bias = b2[t];        }
        else if (t < 192)  { wp = w3 + (t - 128) * 9; bias = b3[t - 128]; }
        else               { wp = w4 + (t - 192) * 9; bias = b4[t - 192]; }
        float i00 = g_pool[(b * HC + t) * 4 + 0];
        float i01 = g_pool[(b * HC + t) * 4 + 1];
        float i10 = g_pool[(b * HC + t) * 4 + 2];
        float i11 = g_pool[(b * HC + t) * 4 + 3];
        catlow[t][0] = i00*wp[4] + i01*wp[5] + i10*wp[7] + i11*wp[8] + bias;
        catlow[t][1] = i00*wp[3] + i01*wp[4] + i10*wp[6] + i11*wp[7] + bias;
        catlow[t][2] = i00*wp[1] + i01*wp[2] + i10*wp[4] + i11*wp[5] + bias;
        catlow[t][3] = i00*wp[0] + i01*wp[1] + i10*wp[3] + i11*wp[4] + bias;
    }
    __syncthreads();
    int o    = oc + (t >> 2);
    int part = t & 3;
    int cc0  = part * 64;
    float a0 = 0.f, a1 = 0.f, a2 = 0.f, a3 = 0.f;
    #pragma unroll 4
    for (int cc = cc0; cc < cc0 + 64; ++cc) {
        float wv = wa[o * CFULL + 256 + cc];
        a0 = fmaf(wv, catlow[cc][0], a0);
        a1 = fmaf(wv, catlow[cc][1], a1);
        a2 = fmaf(wv, catlow[cc][2], a2);
        a3 = fmaf(wv, catlow[cc][3], a3);
    }
    #pragma unroll
    for (int off = 1; off < 4; off <<= 1) {
        a0 += __shfl_xor_sync(0xffffffff, a0, off);
        a1 += __shfl_xor_sync(0xffffffff, a1, off);
        a2 += __shfl_xor_sync(0xffffffff, a2, off);
        a3 += __shfl_xor_sync(0xffffffff, a3, off);
    }
    if (part == 0) {
        float bav = ba[o];
        g_base[(b * 4 + 0) * CFULL + o] = a0 + bav;
        g_base[(b * 4 + 1) * CFULL + o] = a1 + bav;
        g_base[(b * 4 + 2) * CFULL + o] = a2 + bav;
        g_base[(b * 4 + 3) * CFULL + o] = a3 + bav;
    }
}

// ---------------------------------------------------------------------------
// Kernel 3: dwconv3x3 + transpose -> g_x1t[b][p][k] (fp16).
// block = (b, image row), 512 THREADS: kl = tid&31 (channel), ng = tid>>5
// (0..15) -> 8 output cols/thread. Same smem/sync structure as R10 but each
// inter-sync phase is half as long and regs drop to ~55.
// ---------------------------------------------------------------------------
#define STW 137
#define DW_SMEM_BYTES (32 * 3 * STW * 4)   // 52,608

__global__ __launch_bounds__(512) void dwconvT_kernel(
    const float* __restrict__ x, const float* __restrict__ w1, const float* __restrict__ b1)
{
    extern __shared__ float stage[];   // [32 ch][3 rr][STW]
    int row = blockIdx.x & 127;
    int b   = blockIdx.x >> 7;
    int tid = threadIdx.x;
    int kl = tid & 31;
    int ng = tid >> 5;          // 0..15
    int c0 = ng * 8;

    if (tid < 96) {
        int ch = tid / 3, rr = tid - 3 * ch;
        stage[ch * (3 * STW) + rr * STW + 3]   = 0.f;
        stage[ch * (3 * STW) + rr * STW + 132] = 0.f;
    }

    __half* outbase = g_x1t + ((size_t)b * HW + (size_t)row * WW) * HC;

    for (int cc = 0; cc < 8; ++cc) {
        __syncthreads();
        #pragma unroll
        for (int j = 0; j < 6; ++j) {
            int i = tid + 512 * j;          // [0, 3072)
            int c4 = i & 31;
            int g3 = i >> 5;                // [0, 96)
            int ch = g3 / 3;
            int rr = g3 - 3 * ch;
            int gr = row + rr - 1;
            float4 v = make_float4(0.f, 0.f, 0.f, 0.f);
            if (gr >= 0 && gr < HH)
                v = *reinterpret_cast<const float4*>(
                    x + ((size_t)(b * CFULL + cc * 32 + ch)) * HW + gr * WW + c4 * 4);
            float* sp = stage + ch * (3 * STW) + rr * STW + 4 + c4 * 4;
            sp[0] = v.x; sp[1] = v.y; sp[2] = v.z; sp[3] = v.w;
        }
        __syncthreads();
        int k = cc * 32 + kl;
        const float* wp = w1 + k * 9;
        float w00 = wp[0], w01 = wp[1], w02 = wp[2];
        float w10 = wp[3], w11 = wp[4], w12 = wp[5];
        float w20 = wp[6], w21 = wp[7], w22 = wp[8];
        float bias = b1[k];

        float rv[3][10];
        const float* sb = stage + kl * (3 * STW);
        #pragma unroll
        for (int rr = 0; rr < 3; ++rr) {
            #pragma unroll
            for (int i = 0; i < 10; ++i)
                rv[rr][i] = sb[rr * STW + 3 + c0 + i];
        }
        #pragma unroll
        for (int c = 0; c < 8; ++c) {
            float acc = bias;
            acc = fmaf(w00, rv[0][c],     acc);
            acc = fmaf(w01, rv[0][c + 1], acc);
            acc = fmaf(w02, rv[0][c + 2], acc);
            acc = fmaf(w10, rv[1][c],     acc);
            acc = fmaf(w11, rv[1][c + 1], acc);
            acc = fmaf(w12, rv[1][c + 2], acc);
            acc = fmaf(w20, rv[2][c],     acc);
            acc = fmaf(w21, rv[2][c + 1], acc);
            acc = fmaf(w22, rv[2][c + 2], acc);
            outbase[(size_t)(c0 + c) * HC + k] = __float2half_rn(acc);
        }
    }
}

// ---------------------------------------------------------------------------
// Kernel 4: fp16 GEMM (m16n8k16, full ldmatrix, cp.async double buffer,
// BK=32 — R10's measured-best config), fp32 accumulate, direct epilogue.
// A = g_wa_h[m][k], B = g_x1t[n][k], both K-major fp16. D = A * B^T.
// ---------------------------------------------------------------------------
__device__ __forceinline__ float gelu_exact(float v) {
    return 0.5f * v * (1.0f + erff(v * 0.70710678118654752f));
}
__device__ __forceinline__ void mma_f16(float (&d)[4], const uint32_t (&a)[4],
                                        uint32_t b0, uint32_t b1) {
    asm volatile(
        "mma.sync.aligned.m16n8k16.row.col.f32.f16.f16.f32 "
        "{%0,%1,%2,%3}, {%4,%5,%6,%7}, {%8,%9}, {%0,%1,%2,%3};"
        : "+f"(d[0]), "+f"(d[1]), "+f"(d[2]), "+f"(d[3])
        : "r"(a[0]), "r"(a[1]), "r"(a[2]), "r"(a[3]), "r"(b0), "r"(b1));
}
__device__ __forceinline__ void cp_async16(uint32_t dst, const void* src) {
    asm volatile("cp.async.cg.shared.global [%0], [%1], 16;" :: "r"(dst), "l"(src));
}
__device__ __forceinline__ void ldsm4(uint32_t (&r)[4], uint32_t addr) {
    asm volatile("ldmatrix.sync.aligned.m8n8.x4.shared.b16 {%0,%1,%2,%3}, [%4];"
                 : "=r"(r[0]), "=r"(r[1]), "=r"(r[2]), "=r"(r[3]) : "r"(addr));
}

#define BM 128
#define BN 128
#define BK 32
#define HSTR 40                            // halves per smem row (80B: conflict-free)
#define TIL_H (128 * HSTR)                 // halves per tile per stage = 5120
#define GEMM_SMEM_BYTES (4 * TIL_H * 2)    // 40,960

__global__ __launch_bounds__(256, 2) void gemm_gelu_kernel(
    const float* __restrict__ x, float* __restrict__ out)
{
    extern __shared__ __half hsm[];
    // layout: As [2][128][HSTR] halves, then Bs [2][128][HSTR]
    uint32_t as_base = (uint32_t)__cvta_generic_to_shared(hsm);
    uint32_t bs_base = as_base + 2 * TIL_H * 2;

    int m0 = blockIdx.x * BM;              // m-block fastest: B-tile L2 reuse
    int bx = blockIdx.y;                   // image row; n0 = bx*128
    int b  = blockIdx.z;
    int tid = threadIdx.x;
    int lane = tid & 31, warp = tid >> 5;
    int warpM = warp & 3;
    int warpN = warp >> 2;

    const __half* x1b = g_x1t + ((size_t)b * HW + (size_t)bx * WW) * HC;  // [n][256]
    int n0 = bx * BN;

    // cp.async: 128 rows x 4 chunks (8 halves) per tile = 512 chunks, 2/thread
    int rowi[2], kci[2];
    #pragma unroll
    for (int j = 0; j < 2; ++j) {
        int idx = tid + 256 * j;
        rowi[j] = idx >> 2;
        kci[j]  = (idx & 3) * 8;
    }

    auto load_stage = [&](int k0, int s) {
        #pragma unroll
        for (int j = 0; j < 2; ++j) {
            const __half* srcA = g_wa_h + (size_t)(m0 + rowi[j]) * HC + k0 + kci[j];
            uint32_t dstA = as_base + (s * TIL_H + rowi[j] * HSTR + kci[j]) * 2;
            cp_async16(dstA, srcA);
            const __half* srcB = x1b + (size_t)rowi[j] * HC + k0 + kci[j];
            uint32_t dstB = bs_base + (s * TIL_H + rowi[j] * HSTR + kci[j]) * 2;
            cp_async16(dstB, srcB);
        }
        asm volatile("cp.async.commit_group;" ::: "memory");
    };

    // ldmatrix per-lane offsets (halves)
    int j4 = lane >> 3;
    int a_row = ((j4 & 1) * 8) + (lane & 7);
    int a_kc  = (j4 >> 1) * 8;
    int b_row = ((j4 >> 1) * 8) + (lane & 7);
    int b_kc  = (j4 & 1) * 8;
    int aoff0 = (warpM * 32 +  0 + a_row) * HSTR + a_kc;
    int aoff1 = (warpM * 32 + 16 + a_row) * HSTR + a_kc;
    int boff[4];
    #pragma unroll
    for (int ntp = 0; ntp < 4; ++ntp)
        boff[ntp] = (warpN * 64 + ntp * 16 + b_row) * HSTR + b_kc;

    float acc[2][8][4] = {};

    load_stage(0, 0);

    #pragma unroll 1
    for (int it = 0; it < HC / BK; ++it) {
        asm volatile("cp.async.wait_group 0;" ::: "memory");
        __syncthreads();
        if (it < HC / BK - 1) load_stage((it + 1) * BK, (it + 1) & 1);

        int s = it & 1;
        uint32_t aB = as_base + s * TIL_H * 2;
        uint32_t bB = bs_base + s * TIL_H * 2;

        #pragma unroll
        for (int ks = 0; ks < 2; ++ks) {        // two k16 steps per BK=32
            uint32_t af[2][4];
            ldsm4(af[0], aB + (aoff0 + ks * 16) * 2);
            ldsm4(af[1], aB + (aoff1 + ks * 16) * 2);
            #pragma unroll
            for (int ntp = 0; ntp < 4; ++ntp) {
                uint32_t bb[4];
                ldsm4(bb, bB + (boff[ntp] + ks * 16) * 2);
                mma_f16(acc[0][2 * ntp    ], af[0], bb[0], bb[1]);
                mma_f16(acc[1][2 * ntp    ], af[1], bb[0], bb[1]);
                mma_f16(acc[0][2 * ntp + 1], af[0], bb[2], bb[3]);
                mma_f16(acc[1][2 * ntp + 1], af[1], bb[2], bb[3]);
            }
        }
    }

    // Epilogue (direct): +base, exact GELU, gate by x, store.
    int q = ((bx >= 64) ? 2 : 0) + warpN;
    const float* basep = g_base + (b * 4 + q) * CFULL;

    #pragma unroll
    for (int mt = 0; mt < 2; ++mt) {
        int mrow0 = m0 + warpM * 32 + mt * 16 + (lane >> 2);
        int mrow1 = mrow0 + 8;
        float bs0 = basep[mrow0];
        float bs1 = basep[mrow1];
        #pragma unroll
        for (int nt = 0; nt < 8; ++nt) {
            int n = n0 + warpN * 64 + nt * 8 + (lane & 3) * 2;
            size_t off0 = ((size_t)(b * CFULL + mrow0)) * HW + n;
            size_t off1 = ((size_t)(b * CFULL + mrow1)) * HW + n;
            float2 xv0 = *reinterpret_cast<const float2*>(x + off0);
            float2 xv1 = *reinterpret_cast<const float2*>(x + off1);
            float2 r0, r1;
            r0.x = gelu_exact(acc[mt][nt][0] + bs0) * xv0.x;
            r0.y = gelu_exact(acc[mt][nt][1] + bs0) * xv0.y;
            r1.x = gelu_exact(acc[mt][nt][2] + bs1) * xv1.x;
            r1.y = gelu_exact(acc[mt][nt][3] + bs1) * xv1.y;
            *reinterpret_cast<float2*>(out + off0) = r0;
            *reinterpret_cast<float2*>(out + off1) = r1;
        }
    }
}

// ---------------------------------------------------------------------------
extern "C" void kernel_launch(void* const* d_in, const int* in_sizes, int n_in,
                              void* d_out, int out_size) {
    const float* x  = (const float*)d_in[0];
    const float* w1 = (const float*)d_in[1];
    const float* b1 = (const float*)d_in[2];
    const float* w2 = (const float*)d_in[3];
    const float* b2 = (const float*)d_in[4];
    const float* w3 = (const float*)d_in[5];
    const float* b3 = (const float*)d_in[6];
    const float* w4 = (const float*)d_in[7];
    const float* b4 = (const float*)d_in[8];
    const float* wa = (const float*)d_in[9];
    const float* ba = (const float*)d_in[10];
    float* out = (float*)d_out;

    cudaFuncSetAttribute(dwconvT_kernel,
                         cudaFuncAttributeMaxDynamicSharedMemorySize, DW_SMEM_BYTES);
    cudaFuncSetAttribute(gemm_gelu_kernel,
                         cudaFuncAttributeMaxDynamicSharedMemorySize, GEMM_SMEM_BYTES);

    // Fork-join: waconv+pool+base on a side stream, dwconvT on the main
    // (captured) stream, join before the gemm.
    cudaStream_t side;
    cudaStreamCreateWithFlags(&side, cudaStreamNonBlocking);
    cudaEvent_t eFork, eJoin;
    cudaEventCreateWithFlags(&eFork, cudaEventDisableTiming);
    cudaEventCreateWithFlags(&eJoin, cudaEventDisableTiming);

    cudaEventRecord(eFork, 0);
    cudaStreamWaitEvent(side, eFork, 0);

    waconv_kernel<<<512, 256, 0, side>>>(wa);
    pool_kernel<<<BATCH * HC * 4, 256, 0, side>>>(x);
    base_kernel<<<16, 512, 0, side>>>(w2, b2, w3, b3, w4, b4, wa, ba);
    cudaEventRecord(eJoin, side);

    dwconvT_kernel<<<BATCH * HH, 512, DW_SMEM_BYTES>>>(x, w1, b1);

    cudaStreamWaitEvent(0, eJoin, 0);
    gemm_gelu_kernel<<<dim3(CFULL / BM, HH, BATCH), 256, GEMM_SMEM_BYTES>>>(x, out);
}

// round 14
// speedup vs baseline: 1.2900x; 1.0588x over previous
#include <cuda_runtime.h>
#include <cuda_fp16.h>
#include <math.h>
#include <stdint.h>

#define BATCH 4
#define CFULL 512
#define HC 256
#define HH 128
#define WW 128
#define HW (HH*WW)

// x1 transposed + fp16: [b][p(pixel)][k(channel)], k contiguous
__device__ __align__(16) __half g_x1t[BATCH * HW * HC];
__device__ __align__(16) __half g_wa_h[CFULL * HC];   // wa[:, 0:256] in fp16
__device__ float g_pool[BATCH * HC * 4];
__device__ float g_base[BATCH * 4 * CFULL];

// ---------------------------------------------------------------------------
// Kernel 0: convert wa[:, 0:256] to fp16
// ---------------------------------------------------------------------------
__global__ __launch_bounds__(256) void waconv_kernel(const float* __restrict__ wa) {
    int i = blockIdx.x * 256 + threadIdx.x;     // 512*256 = 131072
    int o = i >> 8, k = i & 255;
    g_wa_h[i] = __float2half_rn(wa[o * CFULL + k]);
}

// ---------------------------------------------------------------------------
// Kernel 1: adaptive max pool of channels 256..511 to 2x2
// ---------------------------------------------------------------------------
__global__ __launch_bounds__(256) void pool_kernel(const float* __restrict__ x) {
    int blk = blockIdx.x;
    int q  = blk & 3;
    int cc = (blk >> 2) & 255;
    int b  = blk >> 10;
    int qh = q >> 1, qw = q & 1;
    const float* xin = x + ((size_t)(b * CFULL + 256 + cc)) * HW + qh * 64 * WW + qw * 64;
    const float4* xin4 = reinterpret_cast<const float4*>(xin);

    float m = -INFINITY;
    for (int i = threadIdx.x; i < 1024; i += 256) {
        int r = i >> 4, c4 = i & 15;
        float4 v = xin4[r * 32 + c4];
        m = fmaxf(m, fmaxf(fmaxf(v.x, v.y), fmaxf(v.z, v.w)));
    }
    __shared__ float red[256];
    red[threadIdx.x] = m;
    __syncthreads();
    for (int s = 128; s > 0; s >>= 1) {
        if (threadIdx.x < s) red[threadIdx.x] = fmaxf(red[threadIdx.x], red[threadIdx.x + s]);
        __syncthreads();
    }
    if (threadIdx.x == 0) g_pool[(b * HC + cc) * 4 + q] = red[0];
}

// ---------------------------------------------------------------------------
// Kernel 2: tiny 2x2 dwconvs + base[b][q][o]
// ---------------------------------------------------------------------------
__global__ __launch_bounds__(512) void base_kernel(
    const float* __restrict__ w2, const float* __restrict__ b2,
    const float* __restrict__ w3, const float* __restrict__ b3,
    const float* __restrict__ w4, const float* __restrict__ b4,
    const float* __restrict__ wa, const float* __restrict__ ba)
{
    int b  = blockIdx.x >> 2;
    int oc = (blockIdx.x & 3) * 128;
    __shared__ float catlow[256][4];
    int t = threadIdx.x;
    if (t < 256) {
        const float* wp;
        float bias;
        if (t < 128)       { wp = w2 + t * 9;         bias = b2[t];        }
        else if (t < 192)  { wp = w3 + (t - 128) * 9; bias = b3[t - 128]; }
        else               { wp = w4 + (t - 192) * 9; bias = b4[t - 192]; }
        float i00 = g_pool[(b * HC + t) * 4 + 0];
        float i01 = g_pool[(b * HC + t) * 4 + 1];
        float i10 = g_pool[(b * HC + t) * 4 + 2];
        float i11 = g_pool[(b * HC + t) * 4 + 3];
        catlow[t][0] = i00*wp[4] + i01*wp[5] + i10*wp[7] + i11*wp[8] + bias;
        catlow[t][1] = i00*wp[3] + i01*wp[4] + i10*wp[6] + i11*wp[7] + bias;
        catlow[t][2] = i00*wp[1] + i01*wp[2] + i10*wp[4] + i11*wp[5] + bias;
        catlow[t][3] = i00*wp[0] + i01*wp[1] + i10*wp[3] + i11*wp[4] + bias;
    }
    __syncthreads();
    int o    = oc + (t >> 2);
    int part = t & 3;
    int cc0  = part * 64;
    float a0 = 0.f, a1 = 0.f, a2 = 0.f, a3 = 0.f;
    #pragma unroll 4
    for (int cc = cc0; cc < cc0 + 64; ++cc) {
        float wv = wa[o * CFULL + 256 + cc];
        a0 = fmaf(wv, catlow[cc][0], a0);
        a1 = fmaf(wv, catlow[cc][1], a1);
        a2 = fmaf(wv, catlow[cc][2], a2);
        a3 = fmaf(wv, catlow[cc][3], a3);
    }
    #pragma unroll
    for (int off = 1; off < 4; off <<= 1) {
        a0 += __shfl_xor_sync(0xffffffff, a0, off);
        a1 += __shfl_xor_sync(0xffffffff, a1, off);
        a2 += __shfl_xor_sync(0xffffffff, a2, off);
        a3 += __shfl_xor_sync(0xffffffff, a3, off);
    }
    if (part == 0) {
        float bav = ba[o];
        g_base[(b * 4 + 0) * CFULL + o] = a0 + bav;
        g_base[(b * 4 + 1) * CFULL + o] = a1 + bav;
        g_base[(b * 4 + 2) * CFULL + o] = a2 + bav;
        g_base[(b * 4 + 3) * CFULL + o] = a3 + bav;
    }
}

// ---------------------------------------------------------------------------
// Kernel 3: dwconv3x3 + transpose -> g_x1t[b][p][k] (fp16), 512 threads.
// Stage layout: [32 ch][3 rr] rows of 140 words (4-aligned), channel stride
// 436 words. Window loads vectorized: 2xLDS.128 + 2 scalar per row.
// ---------------------------------------------------------------------------
#define STW 140
#define CHS 436
#define DW_SMEM_BYTES (32 * CHS * 4)   // 55,808

__global__ __launch_bounds__(512) void dwconvT_kernel(
    const float* __restrict__ x, const float* __restrict__ w1, const float* __restrict__ b1)
{
    extern __shared__ float stage[];   // [32 ch][3 rr][STW], ch stride CHS
    int row = blockIdx.x & 127;
    int b   = blockIdx.x >> 7;
    int tid = threadIdx.x;
    int kl = tid & 31;
    int ng = tid >> 5;          // 0..15
    int c0 = ng * 8;

    if (tid < 96) {
        int ch = tid / 3, rr = tid - 3 * ch;
        stage[ch * CHS + rr * STW + 3]   = 0.f;
        stage[ch * CHS + rr * STW + 132] = 0.f;
    }

    __half* outbase = g_x1t + ((size_t)b * HW + (size_t)row * WW) * HC;

    for (int cc = 0; cc < 8; ++cc) {
        __syncthreads();
        #pragma unroll
        for (int j = 0; j < 6; ++j) {
            int i = tid + 512 * j;          // [0, 3072)
            int c4 = i & 31;
            int g3 = i >> 5;                // [0, 96)
            int ch = g3 / 3;
            int rr = g3 - 3 * ch;
            int gr = row + rr - 1;
            float4 v = make_float4(0.f, 0.f, 0.f, 0.f);
            if (gr >= 0 && gr < HH)
                v = *reinterpret_cast<const float4*>(
                    x + ((size_t)(b * CFULL + cc * 32 + ch)) * HW + gr * WW + c4 * 4);
            float* sp = stage + ch * CHS + rr * STW + 4 + c4 * 4;
            *reinterpret_cast<float4*>(sp) = v;
        }
        __syncthreads();
        int k = cc * 32 + kl;
        const float* wp = w1 + k * 9;
        float w00 = wp[0], w01 = wp[1], w02 = wp[2];
        float w10 = wp[3], w11 = wp[4], w12 = wp[5];
        float w20 = wp[6], w21 = wp[7], w22 = wp[8];
        float bias = b1[k];

        float rv[3][10];
        const float* sb = stage + kl * CHS;
        #pragma unroll
        for (int rr = 0; rr < 3; ++rr) {
            int base = rr * STW + 3 + c0;   // word (8ng+3); base+1 is 16B-aligned
            rv[rr][0] = sb[base];
            float4 v1 = *reinterpret_cast<const float4*>(sb + base + 1);
            float4 v2 = *reinterpret_cast<const float4*>(sb + base + 5);
            rv[rr][1] = v1.x; rv[rr][2] = v1.y; rv[rr][3] = v1.z; rv[rr][4] = v1.w;
            rv[rr][5] = v2.x; rv[rr][6] = v2.y; rv[rr][7] = v2.z; rv[rr][8] = v2.w;
            rv[rr][9] = sb[base + 9];
        }
        #pragma unroll
        for (int c = 0; c < 8; ++c) {
            float acc = bias;
            acc = fmaf(w00, rv[0][c],     acc);
            acc = fmaf(w01, rv[0][c + 1], acc);
            acc = fmaf(w02, rv[0][c + 2], acc);
            acc = fmaf(w10, rv[1][c],     acc);
            acc = fmaf(w11, rv[1][c + 1], acc);
            acc = fmaf(w12, rv[1][c + 2], acc);
            acc = fmaf(w20, rv[2][c],     acc);
            acc = fmaf(w21, rv[2][c + 1], acc);
            acc = fmaf(w22, rv[2][c + 2], acc);
            outbase[(size_t)(c0 + c) * HC + k] = __float2half_rn(acc);
        }
    }
}

// ---------------------------------------------------------------------------
// Kernel 4: fp16 GEMM (m16n8k16, full ldmatrix, 4-stage cp.async pipeline
// with wait_group 2), fp32 accumulate, direct epilogue.
// A = g_wa_h[m][k], B = g_x1t[n][k], both K-major fp16. D = A * B^T.
// ---------------------------------------------------------------------------
__device__ __forceinline__ float gelu_exact(float v) {
    return 0.5f * v * (1.0f + erff(v * 0.70710678118654752f));
}
__device__ __forceinline__ void mma_f16(float (&d)[4], const uint32_t (&a)[4],
                                        uint32_t b0, uint32_t b1) {
    asm volatile(
        "mma.sync.aligned.m16n8k16.row.col.f32.f16.f16.f32 "
        "{%0,%1,%2,%3}, {%4,%5,%6,%7}, {%8,%9}, {%0,%1,%2,%3};"
        : "+f"(d[0]), "+f"(d[1]), "+f"(d[2]), "+f"(d[3])
        : "r"(a[0]), "r"(a[1]), "r"(a[2]), "r"(a[3]), "r"(b0), "r"(b1));
}
__device__ __forceinline__ void cp_async16(uint32_t dst, const void* src) {
    asm volatile("cp.async.cg.shared.global [%0], [%1], 16;" :: "r"(dst), "l"(src));
}
__device__ __forceinline__ void ldsm4(uint32_t (&r)[4], uint32_t addr) {
    asm volatile("ldmatrix.sync.aligned.m8n8.x4.shared.b16 {%0,%1,%2,%3}, [%4];"
                 : "=r"(r[0]), "=r"(r[1]), "=r"(r[2]), "=r"(r[3]) : "r"(addr));
}

#define BM 128
#define BN 128
#define BK 32
#define NSTAGE 4
#define HSTR 40                            // halves per smem row (80B: conflict-free)
#define TIL_H (128 * HSTR)                 // halves per tile per stage = 5120
#define GEMM_SMEM_BYTES (NSTAGE * 2 * TIL_H * 2)   // 81,920

__global__ __launch_bounds__(256, 2) void gemm_gelu_kernel(
    const float* __restrict__ x, float* __restrict__ out)
{
    extern __shared__ __half hsm[];
    // layout: per stage s: As at s*2*TIL_H, Bs at s*2*TIL_H + TIL_H (halves)
    uint32_t sm_base = (uint32_t)__cvta_generic_to_shared(hsm);

    int m0 = blockIdx.x * BM;              // m-block fastest: B-tile L2 reuse
    int bx = blockIdx.y;                   // image row; n0 = bx*128
    int b  = blockIdx.z;
    int tid = threadIdx.x;
    int lane = tid & 31, warp = tid >> 5;
    int warpM = warp & 3;
    int warpN = warp >> 2;

    const __half* x1b = g_x1t + ((size_t)b * HW + (size_t)bx * WW) * HC;  // [n][256]
    int n0 = bx * BN;

    // cp.async: 128 rows x 4 chunks (8 halves) per tile = 512 chunks, 2/thread
    int rowi[2], kci[2];
    #pragma unroll
    for (int j = 0; j < 2; ++j) {
        int idx = tid + 256 * j;
        rowi[j] = idx >> 2;
        kci[j]  = (idx & 3) * 8;
    }

    auto load_stage = [&](int k0, int s) {
        uint32_t sa = sm_base + (s * 2 * TIL_H) * 2;
        uint32_t sb = sa + TIL_H * 2;
        #pragma unroll
        for (int j = 0; j < 2; ++j) {
            const __half* srcA = g_wa_h + (size_t)(m0 + rowi[j]) * HC + k0 + kci[j];
            cp_async16(sa + (rowi[j] * HSTR + kci[j]) * 2, srcA);
            const __half* srcB = x1b + (size_t)rowi[j] * HC + k0 + kci[j];
            cp_async16(sb + (rowi[j] * HSTR + kci[j]) * 2, srcB);
        }
        asm volatile("cp.async.commit_group;" ::: "memory");
    };

    // ldmatrix per-lane offsets (halves)
    int j4 = lane >> 3;
    int a_row = ((j4 & 1) * 8) + (lane & 7);
    int a_kc  = (j4 >> 1) * 8;
    int b_row = ((j4 >> 1) * 8) + (lane & 7);
    int b_kc  = (j4 & 1) * 8;
    int aoff0 = (warpM * 32 +  0 + a_row) * HSTR + a_kc;
    int aoff1 = (warpM * 32 + 16 + a_row) * HSTR + a_kc;
    int boff[4];
    #pragma unroll
    for (int ntp = 0; ntp < 4; ++ntp)
        boff[ntp] = (warpN * 64 + ntp * 16 + b_row) * HSTR + b_kc;

    float acc[2][8][4] = {};

    load_stage(0, 0);
    load_stage(BK, 1);
    load_stage(2 * BK, 2);

    #pragma unroll 1
    for (int it = 0; it < HC / BK; ++it) {
        if (it <= 5)      asm volatile("cp.async.wait_group 2;" ::: "memory");
        else if (it == 6) asm volatile("cp.async.wait_group 1;" ::: "memory");
        else              asm volatile("cp.async.wait_group 0;" ::: "memory");
        __syncthreads();
        if (it + 3 < HC / BK) load_stage((it + 3) * BK, (it + 3) & (NSTAGE - 1));

        int s = it & (NSTAGE - 1);
        uint32_t aB = sm_base + (s * 2 * TIL_H) * 2;
        uint32_t bB = aB + TIL_H * 2;

        #pragma unroll
        for (int ks = 0; ks < 2; ++ks) {        // two k16 steps per BK=32
            uint32_t af[2][4];
            ldsm4(af[0], aB + (aoff0 + ks * 16) * 2);
            ldsm4(af[1], aB + (aoff1 + ks * 16) * 2);
            #pragma unroll
            for (int ntp = 0; ntp < 4; ++ntp) {
                uint32_t bb[4];
                ldsm4(bb, bB + (boff[ntp] + ks * 16) * 2);
                mma_f16(acc[0][2 * ntp    ], af[0], bb[0], bb[1]);
                mma_f16(acc[1][2 * ntp    ], af[1], bb[0], bb[1]);
                mma_f16(acc[0][2 * ntp + 1], af[0], bb[2], bb[3]);
                mma_f16(acc[1][2 * ntp + 1], af[1], bb[2], bb[3]);
            }
        }
    }

    // Epilogue (direct): +base, exact GELU, gate by x, store.
    int q = ((bx >= 64) ? 2 : 0) + warpN;
    const float* basep = g_base + (b * 4 + q) * CFULL;

    #pragma unroll
    for (int mt = 0; mt < 2; ++mt) {
        int mrow0 = m0 + warpM * 32 + mt * 16 + (lane >> 2);
        int mrow1 = mrow0 + 8;
        float bs0 = basep[mrow0];
        float bs1 = basep[mrow1];
        #pragma unroll
        for (int nt = 0; nt < 8; ++nt) {
            int n = n0 + warpN * 64 + nt * 8 + (lane & 3) * 2;
            size_t off0 = ((size_t)(b * CFULL + mrow0)) * HW + n;
            size_t off1 = ((size_t)(b * CFULL + mrow1)) * HW + n;
            float2 xv0 = *reinterpret_cast<const float2*>(x + off0);
            float2 xv1 = *reinterpret_cast<const float2*>(x + off1);
            float2 r0, r1;
            r0.x = gelu_exact(acc[mt][nt][0] + bs0) * xv0.x;
            r0.y = gelu_exact(acc[mt][nt][1] + bs0) * xv0.y;
            r1.x = gelu_exact(acc[mt][nt][2] + bs1) * xv1.x;
            r1.y = gelu_exact(acc[mt][nt][3] + bs1) * xv1.y;
            *reinterpret_cast<float2*>(out + off0) = r0;
            *reinterpret_cast<float2*>(out + off1) = r1;
        }
    }
}

// ---------------------------------------------------------------------------
extern "C" void kernel_launch(void* const* d_in, const int* in_sizes, int n_in,
                              void* d_out, int out_size) {
    const float* x  = (const float*)d_in[0];
    const float* w1 = (const float*)d_in[1];
    const float* b1 = (const float*)d_in[2];
    const float* w2 = (const float*)d_in[3];
    const float* b2 = (const float*)d_in[4];
    const float* w3 = (const float*)d_in[5];
    const float* b3 = (const float*)d_in[6];
    const float* w4 = (const float*)d_in[7];
    const float* b4 = (const float*)d_in[8];
    const float* wa = (const float*)d_in[9];
    const float* ba = (const float*)d_in[10];
    float* out = (float*)d_out;

    cudaFuncSetAttribute(dwconvT_kernel,
                         cudaFuncAttributeMaxDynamicSharedMemorySize, DW_SMEM_BYTES);
    cudaFuncSetAttribute(gemm_gelu_kernel,
                         cudaFuncAttributeMaxDynamicSharedMemorySize, GEMM_SMEM_BYTES);

    // Fork-join: waconv+pool+base on a side stream, dwconvT on the main
    // (captured) stream, join before the gemm.
    cudaStream_t side;
    cudaStreamCreateWithFlags(&side, cudaStreamNonBlocking);
    cudaEvent_t eFork, eJoin;
    cudaEventCreateWithFlags(&eFork, cudaEventDisableTiming);
    cudaEventCreateWithFlags(&eJoin, cudaEventDisableTiming);

    cudaEventRecord(eFork, 0);
    cudaStreamWaitEvent(side, eFork, 0);

    waconv_kernel<<<512, 256, 0, side>>>(wa);
    pool_kernel<<<BATCH * HC * 4, 256, 0, side>>>(x);
    base_kernel<<<16, 512, 0, side>>>(w2, b2, w3, b3, w4, b4, wa, ba);
    cudaEventRecord(eJoin, side);

    dwconvT_kernel<<<BATCH * HH, 512, DW_SMEM_BYTES>>>(x, w1, b1);

    cudaStreamWaitEvent(0, eJoin, 0);
    gemm_gelu_kernel<<<dim3(CFULL / BM, HH, BATCH), 256, GEMM_SMEM_BYTES>>>(x, out);
}